// round 7
// baseline (speedup 1.0000x reference)
#include <cuda_runtime.h>

#define N_NODES 8192
#define NV4 (N_NODES / 4)       // 2048 float4 per row
#define PSI 64
#define GRID_EN 148             // 1 block/SM, all co-resident -> grid barrier OK
#define THREADS_EN 512

// __device__ scratch (no allocations allowed).
// g_agg zero-init at load; fused kernel reads-then-zeros it each replay.
__device__ float g_agg[N_NODES];
__device__ float g_t[N_NODES];
__device__ float g_s[N_NODES];

// grid barrier state (monotone generation; replay-safe)
__device__ unsigned int g_bar_count = 0;
__device__ volatile unsigned int g_bar_gen = 0;

// ---------------------------------------------------------------------------
// K1: fused edge MLP + scatter-add, grid barrier, node MLP -> t = struct^2.
// Grid = 148 blocks x 512 threads, all resident (1 block/SM), so the
// software grid barrier is deadlock-free and ~1us.
// ---------------------------------------------------------------------------
__global__ __launch_bounds__(THREADS_EN) void k_edge_node(
        const int4* __restrict__ col4,
        const float4* __restrict__ val4,
        const float* __restrict__ w1e, const float* __restrict__ b1e,
        const float* __restrict__ w2e, const float* __restrict__ b2e,
        const float* __restrict__ w1n, const float* __restrict__ b1n,
        const float* __restrict__ w2n, const float* __restrict__ b2n,
        int nnz4) {
    __shared__ float sw1[PSI], sb1[PSI], sw2[PSI];
    __shared__ float sb2s;

    const int tid = threadIdx.x;
    const int gtid = blockIdx.x * THREADS_EN + tid;
    const int gstride = GRID_EN * THREADS_EN;      // 75776

    // ---- phase A: edge MLP + scatter ----
    if (tid < PSI) {
        sw1[tid] = w1e[tid];
        sb1[tid] = b1e[tid];
        sw2[tid] = w2e[tid];
    }
    if (tid == 0) sb2s = b2e[0];
    __syncthreads();

    for (int i = gtid; i < nnz4; i += gstride) {
        float4 v = val4[i];
        int4   c = col4[i];
        float a0 = sb2s, a1 = sb2s, a2 = sb2s, a3 = sb2s;
#pragma unroll
        for (int j = 0; j < PSI; j++) {
            float w = sw1[j], b = sb1[j], u = sw2[j];
            a0 = fmaf(fmaxf(fmaf(v.x, w, b), 0.0f), u, a0);
            a1 = fmaf(fmaxf(fmaf(v.y, w, b), 0.0f), u, a1);
            a2 = fmaf(fmaxf(fmaf(v.z, w, b), 0.0f), u, a2);
            a3 = fmaf(fmaxf(fmaf(v.w, w, b), 0.0f), u, a3);
        }
        atomicAdd(&g_agg[c.x], a0);
        atomicAdd(&g_agg[c.y], a1);
        atomicAdd(&g_agg[c.z], a2);
        atomicAdd(&g_agg[c.w], a3);
    }

    // ---- grid barrier (all 148 blocks resident) ----
    __syncthreads();
    if (tid == 0) {
        __threadfence();
        unsigned int gen = g_bar_gen;
        if (atomicAdd(&g_bar_count, 1u) == GRID_EN - 1u) {
            g_bar_count = 0;
            __threadfence();
            g_bar_gen = gen + 1u;
        } else {
            while (g_bar_gen == gen) { }
        }
        __threadfence();
    }
    __syncthreads();

    // ---- phase B: node MLP -> t = struct^2, re-zero g_agg ----
    if (tid < PSI) {
        sw1[tid] = w1n[tid];
        sb1[tid] = b1n[tid];
        sw2[tid] = w2n[tid];
    }
    if (tid == 0) sb2s = b2n[0];
    __syncthreads();

    for (int n = gtid; n < N_NODES; n += gstride) {
        float x = g_agg[n];
        g_agg[n] = 0.0f;                        // reset for next graph replay
        float acc = sb2s;
#pragma unroll
        for (int j = 0; j < PSI; j++) {
            float h = fmaf(x, sw1[j], sb1[j]);
            acc = fmaf(fmaxf(h, 0.0f), sw2[j], acc);
        }
        g_t[n] = acc * acc;
    }
}

// ---------------------------------------------------------------------------
// K2: row score (unchanged from R6 — at the LTS structural ceiling).
// s[r] = sum_n adj[r,n]^2 * t[n];  2 rows per 256-thread block, grid 4096.
// ---------------------------------------------------------------------------
__global__ __launch_bounds__(256) void k_row_score(const float* __restrict__ adj) {
    const int row0 = blockIdx.x * 2;
    const float4* __restrict__ a0 =
        reinterpret_cast<const float4*>(adj + (size_t)row0 * N_NODES);
    const float4* __restrict__ a1 = a0 + NV4;
    const float4* __restrict__ tv = reinterpret_cast<const float4*>(g_t);

    float s0 = 0.0f, s1 = 0.0f;
#pragma unroll 2
    for (int i = threadIdx.x; i < NV4; i += 256) {
        float4 v0 = __ldcs(&a0[i]);
        float4 v1 = __ldcs(&a1[i]);
        float4 tw = __ldg(&tv[i]);
        s0 = fmaf(v0.x * v0.x, tw.x, s0);
        s0 = fmaf(v0.y * v0.y, tw.y, s0);
        s0 = fmaf(v0.z * v0.z, tw.z, s0);
        s0 = fmaf(v0.w * v0.w, tw.w, s0);
        s1 = fmaf(v1.x * v1.x, tw.x, s1);
        s1 = fmaf(v1.y * v1.y, tw.y, s1);
        s1 = fmaf(v1.z * v1.z, tw.z, s1);
        s1 = fmaf(v1.w * v1.w, tw.w, s1);
    }

#pragma unroll
    for (int off = 16; off > 0; off >>= 1) {
        s0 += __shfl_down_sync(0xffffffffu, s0, off);
        s1 += __shfl_down_sync(0xffffffffu, s1, off);
    }
    __shared__ float warp_sum[8][2];
    if ((threadIdx.x & 31) == 0) {
        warp_sum[threadIdx.x >> 5][0] = s0;
        warp_sum[threadIdx.x >> 5][1] = s1;
    }
    __syncthreads();
    if (threadIdx.x < 16) {
        float v = warp_sum[threadIdx.x & 7][threadIdx.x >> 3];
        v += __shfl_down_sync(0xffffu, v, 4, 8);
        v += __shfl_down_sync(0xffffu, v, 2, 8);
        v += __shfl_down_sync(0xffffu, v, 1, 8);
        if ((threadIdx.x & 7) == 0) g_s[row0 + (threadIdx.x >> 3)] = v;
    }
}

// ---------------------------------------------------------------------------
// K3: gather per-edge output (exactly E threads)
// ---------------------------------------------------------------------------
__global__ __launch_bounds__(512) void k_gather(const int* __restrict__ src_nodes,
                                                float* __restrict__ out, int E) {
    int e = blockIdx.x * 512 + threadIdx.x;
    if (e < E) out[e] = g_s[src_nodes[e]];
}

// ---------------------------------------------------------------------------
// launch
// Inputs (metadata order): col, values, adj, src_nodes,
//                          w1e, b1e, w2e, b2e, w1n, b1n, w2n, b2n
// ---------------------------------------------------------------------------
extern "C" void kernel_launch(void* const* d_in, const int* in_sizes, int n_in,
                              void* d_out, int out_size) {
    const int*   col       = (const int*)d_in[0];
    const float* values    = (const float*)d_in[1];
    const float* adj       = (const float*)d_in[2];
    const int*   src_nodes = (const int*)d_in[3];
    const float* w1e = (const float*)d_in[4];
    const float* b1e = (const float*)d_in[5];
    const float* w2e = (const float*)d_in[6];
    const float* b2e = (const float*)d_in[7];
    const float* w1n = (const float*)d_in[8];
    const float* b1n = (const float*)d_in[9];
    const float* w2n = (const float*)d_in[10];
    const float* b2n = (const float*)d_in[11];
    float* out = (float*)d_out;

    const int nnz = in_sizes[0];   // 262144, divisible by 4
    const int E   = in_sizes[3];

    k_edge_node<<<GRID_EN, THREADS_EN>>>(
        (const int4*)col, (const float4*)values,
        w1e, b1e, w2e, b2e, w1n, b1n, w2n, b2n, nnz / 4);
    k_row_score<<<N_NODES / 2, 256>>>(adj);
    k_gather<<<(E + 511) / 512, 512>>>(src_nodes, out, E);
}

// round 8
// speedup vs baseline: 1.2300x; 1.2300x over previous
#include <cuda_runtime.h>

#define N_NODES 8192
#define NV4 (N_NODES / 4)       // 2048 float4 per row
#define PSI 64

// __device__ scratch (no allocations allowed).
// g_agg zero-init at load; node_mlp reads-then-zeros it each replay.
__device__ float g_agg[N_NODES];
__device__ float g_t[N_NODES];
__device__ float g_s[N_NODES];

// ---------------------------------------------------------------------------
// Kernel 1: edge MLP + scatter-add by col.  4 edges per thread.
// ---------------------------------------------------------------------------
__global__ __launch_bounds__(512) void k_edge_scatter(
        const int4* __restrict__ col4,
        const float4* __restrict__ val4,
        const float* __restrict__ w1,
        const float* __restrict__ b1,
        const float* __restrict__ w2,
        const float* __restrict__ b2,
        int nnz4) {
    __shared__ float sw1[PSI], sb1[PSI], sw2[PSI], sb2;
    if (threadIdx.x < PSI) {
        sw1[threadIdx.x] = w1[threadIdx.x];
        sb1[threadIdx.x] = b1[threadIdx.x];
        sw2[threadIdx.x] = w2[threadIdx.x];
    }
    if (threadIdx.x == 0) sb2 = b2[0];
    __syncthreads();

    int i = blockIdx.x * blockDim.x + threadIdx.x;
    if (i >= nnz4) return;
    float4 v = val4[i];
    int4   c = col4[i];
    float a0 = sb2, a1 = sb2, a2 = sb2, a3 = sb2;
#pragma unroll
    for (int j = 0; j < PSI; j++) {
        float w = sw1[j], b = sb1[j], u = sw2[j];
        a0 = fmaf(fmaxf(fmaf(v.x, w, b), 0.0f), u, a0);
        a1 = fmaf(fmaxf(fmaf(v.y, w, b), 0.0f), u, a1);
        a2 = fmaf(fmaxf(fmaf(v.z, w, b), 0.0f), u, a2);
        a3 = fmaf(fmaxf(fmaf(v.w, w, b), 0.0f), u, a3);
    }
    atomicAdd(&g_agg[c.x], a0);
    atomicAdd(&g_agg[c.y], a1);
    atomicAdd(&g_agg[c.z], a2);
    atomicAdd(&g_agg[c.w], a3);
}

// ---------------------------------------------------------------------------
// Kernel 2: node MLP, store struct^2, re-zero g_agg for the next replay.
// PDL secondary: waits on edge_scatter via grid-dependency sync.
// ---------------------------------------------------------------------------
__global__ __launch_bounds__(512) void k_node_mlp(
        const float* __restrict__ w1,
        const float* __restrict__ b1,
        const float* __restrict__ w2,
        const float* __restrict__ b2) {
    __shared__ float sw1[PSI], sb1[PSI], sw2[PSI], sb2;
    if (threadIdx.x < PSI) {
        sw1[threadIdx.x] = w1[threadIdx.x];
        sb1[threadIdx.x] = b1[threadIdx.x];
        sw2[threadIdx.x] = w2[threadIdx.x];
    }
    if (threadIdx.x == 0) sb2 = b2[0];
    __syncthreads();

    cudaGridDependencySynchronize();   // all g_agg atomics visible

    int i = blockIdx.x * blockDim.x + threadIdx.x;
    if (i >= N_NODES) return;
    float x = g_agg[i];
    g_agg[i] = 0.0f;              // reset for next graph replay
    float acc = sb2;
#pragma unroll
    for (int j = 0; j < PSI; j++) {
        float h = fmaf(x, sw1[j], sb1[j]);
        acc = fmaf(fmaxf(h, 0.0f), sw2[j], acc);
    }
    g_t[i] = acc * acc;
}

// ---------------------------------------------------------------------------
// Kernel 3: row score.  s[r] = sum_n adj[r,n]^2 * t[n]
// 2 rows per 256-thread block, grid 4096.  At the HBM/LTS streaming ceiling.
// PDL secondary: sync before first use of g_t.
// ---------------------------------------------------------------------------
__global__ __launch_bounds__(256) void k_row_score(const float* __restrict__ adj) {
    const int row0 = blockIdx.x * 2;
    const float4* __restrict__ a0 =
        reinterpret_cast<const float4*>(adj + (size_t)row0 * N_NODES);
    const float4* __restrict__ a1 = a0 + NV4;
    const float4* __restrict__ tv = reinterpret_cast<const float4*>(g_t);

    cudaGridDependencySynchronize();   // g_t ready

    float s0 = 0.0f, s1 = 0.0f;
#pragma unroll 2
    for (int i = threadIdx.x; i < NV4; i += 256) {
        float4 v0 = __ldcs(&a0[i]);
        float4 v1 = __ldcs(&a1[i]);
        float4 tw = __ldg(&tv[i]);
        s0 = fmaf(v0.x * v0.x, tw.x, s0);
        s0 = fmaf(v0.y * v0.y, tw.y, s0);
        s0 = fmaf(v0.z * v0.z, tw.z, s0);
        s0 = fmaf(v0.w * v0.w, tw.w, s0);
        s1 = fmaf(v1.x * v1.x, tw.x, s1);
        s1 = fmaf(v1.y * v1.y, tw.y, s1);
        s1 = fmaf(v1.z * v1.z, tw.z, s1);
        s1 = fmaf(v1.w * v1.w, tw.w, s1);
    }

#pragma unroll
    for (int off = 16; off > 0; off >>= 1) {
        s0 += __shfl_down_sync(0xffffffffu, s0, off);
        s1 += __shfl_down_sync(0xffffffffu, s1, off);
    }
    __shared__ float warp_sum[8][2];
    if ((threadIdx.x & 31) == 0) {
        warp_sum[threadIdx.x >> 5][0] = s0;
        warp_sum[threadIdx.x >> 5][1] = s1;
    }
    __syncthreads();
    if (threadIdx.x < 16) {
        float v = warp_sum[threadIdx.x & 7][threadIdx.x >> 3];
        v += __shfl_down_sync(0xffffu, v, 4, 8);
        v += __shfl_down_sync(0xffffu, v, 2, 8);
        v += __shfl_down_sync(0xffffu, v, 1, 8);
        if ((threadIdx.x & 7) == 0) g_s[row0 + (threadIdx.x >> 3)] = v;
    }
}

// ---------------------------------------------------------------------------
// Kernel 4: gather per-edge output, 4 edges per thread (int4/float4).
// PDL secondary: sync before reading g_s.
// ---------------------------------------------------------------------------
__global__ __launch_bounds__(512) void k_gather(const int4* __restrict__ src4,
                                                float4* __restrict__ out4, int E4) {
    int e = blockIdx.x * 512 + threadIdx.x;
    cudaGridDependencySynchronize();   // g_s ready
    if (e < E4) {
        int4 c = src4[e];
        float4 o;
        o.x = g_s[c.x];
        o.y = g_s[c.y];
        o.z = g_s[c.z];
        o.w = g_s[c.w];
        out4[e] = o;
    }
}

// ---------------------------------------------------------------------------
// launch helper: PDL launch (programmatic stream serialization)
// ---------------------------------------------------------------------------
template <typename... Args>
static inline void launch_pdl(void (*kern)(Args...), dim3 grid, dim3 block,
                              Args... args) {
    cudaLaunchAttribute attr[1];
    attr[0].id = cudaLaunchAttributeProgrammaticStreamSerialization;
    attr[0].val.programmaticStreamSerializationAllowed = 1;
    cudaLaunchConfig_t cfg{};
    cfg.gridDim = grid;
    cfg.blockDim = block;
    cfg.dynamicSmemBytes = 0;
    cfg.stream = 0;            // legacy default stream (the captured stream)
    cfg.attrs = attr;
    cfg.numAttrs = 1;
    cudaLaunchKernelEx(&cfg, kern, args...);
}

// ---------------------------------------------------------------------------
// launch
// Inputs (metadata order): col, values, adj, src_nodes,
//                          w1e, b1e, w2e, b2e, w1n, b1n, w2n, b2n
// ---------------------------------------------------------------------------
extern "C" void kernel_launch(void* const* d_in, const int* in_sizes, int n_in,
                              void* d_out, int out_size) {
    const int*   col       = (const int*)d_in[0];
    const float* values    = (const float*)d_in[1];
    const float* adj       = (const float*)d_in[2];
    const int*   src_nodes = (const int*)d_in[3];
    const float* w1e = (const float*)d_in[4];
    const float* b1e = (const float*)d_in[5];
    const float* w2e = (const float*)d_in[6];
    const float* b2e = (const float*)d_in[7];
    const float* w1n = (const float*)d_in[8];
    const float* b1n = (const float*)d_in[9];
    const float* w2n = (const float*)d_in[10];
    const float* b2n = (const float*)d_in[11];
    float* out = (float*)d_out;

    const int nnz = in_sizes[0];   // 262144, divisible by 4
    const int E   = in_sizes[3];   // 32768, divisible by 4

    const int nnz4 = nnz / 4;
    const int E4   = E / 4;

    // primary: plain launch
    k_edge_scatter<<<(nnz4 + 511) / 512, 512>>>(
        (const int4*)col, (const float4*)values, w1e, b1e, w2e, b2e, nnz4);

    // dependents: PDL so their launch/ramp overlaps the predecessor's drain
    launch_pdl(k_node_mlp, dim3((N_NODES + 511) / 512), dim3(512),
               w1n, b1n, w2n, b2n);
    launch_pdl(k_row_score, dim3(N_NODES / 2), dim3(256), adj);
    launch_pdl(k_gather, dim3((E4 + 511) / 512), dim3(512),
               (const int4*)src_nodes, (float4*)out, E4);
}

// round 9
// speedup vs baseline: 1.2549x; 1.0202x over previous
#include <cuda_runtime.h>

#define N_NODES 8192
#define NV4 (N_NODES / 4)       // 2048 float4 per row
#define PSI 64
#define GRID_RS 1184            // 148 SMs x 8 blocks, grid-stride over rows

// __device__ scratch (no allocations allowed).
// g_agg zero-init at load; node_mlp reads-then-zeros it each replay.
__device__ float g_agg[N_NODES];
__device__ float g_t[N_NODES];
__device__ float g_s[N_NODES];

// ---------------------------------------------------------------------------
// Kernel 1: edge MLP + scatter-add by col.  1 edge per thread (short chains,
// 262144 threads -> latency well hidden).
// ---------------------------------------------------------------------------
__global__ __launch_bounds__(256) void k_edge_scatter(
        const int* __restrict__ col,
        const float* __restrict__ values,
        const float* __restrict__ w1,
        const float* __restrict__ b1,
        const float* __restrict__ w2,
        const float* __restrict__ b2,
        int nnz) {
    __shared__ float sw1[PSI], sb1[PSI], sw2[PSI], sb2;
    if (threadIdx.x < PSI) {
        sw1[threadIdx.x] = w1[threadIdx.x];
        sb1[threadIdx.x] = b1[threadIdx.x];
        sw2[threadIdx.x] = w2[threadIdx.x];
    }
    if (threadIdx.x == 0) sb2 = b2[0];
    __syncthreads();

    int i = blockIdx.x * 256 + threadIdx.x;
    if (i >= nnz) return;
    float v = values[i];
    // 4 independent partial accumulators to break the serial FMA chain
    float p0 = 0.0f, p1 = 0.0f, p2 = 0.0f, p3 = 0.0f;
#pragma unroll
    for (int j = 0; j < PSI; j += 4) {
        p0 = fmaf(fmaxf(fmaf(v, sw1[j+0], sb1[j+0]), 0.0f), sw2[j+0], p0);
        p1 = fmaf(fmaxf(fmaf(v, sw1[j+1], sb1[j+1]), 0.0f), sw2[j+1], p1);
        p2 = fmaf(fmaxf(fmaf(v, sw1[j+2], sb1[j+2]), 0.0f), sw2[j+2], p2);
        p3 = fmaf(fmaxf(fmaf(v, sw1[j+3], sb1[j+3]), 0.0f), sw2[j+3], p3);
    }
    atomicAdd(&g_agg[col[i]], sb2 + (p0 + p1) + (p2 + p3));
}

// ---------------------------------------------------------------------------
// Kernel 2: node MLP, store struct^2, re-zero g_agg for the next replay.
// PDL secondary.
// ---------------------------------------------------------------------------
__global__ __launch_bounds__(512) void k_node_mlp(
        const float* __restrict__ w1,
        const float* __restrict__ b1,
        const float* __restrict__ w2,
        const float* __restrict__ b2) {
    __shared__ float sw1[PSI], sb1[PSI], sw2[PSI], sb2;
    if (threadIdx.x < PSI) {
        sw1[threadIdx.x] = w1[threadIdx.x];
        sb1[threadIdx.x] = b1[threadIdx.x];
        sw2[threadIdx.x] = w2[threadIdx.x];
    }
    if (threadIdx.x == 0) sb2 = b2[0];
    __syncthreads();

    cudaGridDependencySynchronize();   // all g_agg atomics visible

    int i = blockIdx.x * 512 + threadIdx.x;
    if (i >= N_NODES) return;
    float x = g_agg[i];
    g_agg[i] = 0.0f;              // reset for next graph replay
    float p0 = 0.0f, p1 = 0.0f, p2 = 0.0f, p3 = 0.0f;
#pragma unroll
    for (int j = 0; j < PSI; j += 4) {
        p0 = fmaf(fmaxf(fmaf(x, sw1[j+0], sb1[j+0]), 0.0f), sw2[j+0], p0);
        p1 = fmaf(fmaxf(fmaf(x, sw1[j+1], sb1[j+1]), 0.0f), sw2[j+1], p1);
        p2 = fmaf(fmaxf(fmaf(x, sw1[j+2], sb1[j+2]), 0.0f), sw2[j+2], p2);
        p3 = fmaf(fmaxf(fmaf(x, sw1[j+3], sb1[j+3]), 0.0f), sw2[j+3], p3);
    }
    float acc = sb2 + (p0 + p1) + (p2 + p3);
    g_t[i] = acc * acc;
}

// ---------------------------------------------------------------------------
// Kernel 3: row score.  s[r] = sum_n adj[r,n]^2 * t[n]
// Grid-stride over rows, grid = 1184 (8 blocks/SM), R1's proven low-register
// 1-row body (32 regs, occ ~95%).  No wave tails: every block processes
// ceil(8192/1184) rows back-to-back.  PDL secondary.
// ---------------------------------------------------------------------------
__global__ __launch_bounds__(256, 8) void k_row_score(const float* __restrict__ adj) {
    __shared__ float warp_sum[8];
    const float4* __restrict__ tv = reinterpret_cast<const float4*>(g_t);

    cudaGridDependencySynchronize();   // g_t ready

    for (int row = blockIdx.x; row < N_NODES; row += GRID_RS) {
        const float4* __restrict__ a =
            reinterpret_cast<const float4*>(adj + (size_t)row * N_NODES);
        float acc = 0.0f;
#pragma unroll 4
        for (int i = threadIdx.x; i < NV4; i += 256) {
            float4 av = __ldcs(&a[i]);
            float4 tw = __ldg(&tv[i]);
            acc = fmaf(av.x * av.x, tw.x, acc);
            acc = fmaf(av.y * av.y, tw.y, acc);
            acc = fmaf(av.z * av.z, tw.z, acc);
            acc = fmaf(av.w * av.w, tw.w, acc);
        }
#pragma unroll
        for (int off = 16; off > 0; off >>= 1)
            acc += __shfl_down_sync(0xffffffffu, acc, off);
        if ((threadIdx.x & 31) == 0) warp_sum[threadIdx.x >> 5] = acc;
        __syncthreads();
        if (threadIdx.x < 8) {
            float v = warp_sum[threadIdx.x];
#pragma unroll
            for (int off = 4; off > 0; off >>= 1)
                v += __shfl_down_sync(0xffu, v, off);
            if (threadIdx.x == 0) g_s[row] = v;
        }
        __syncthreads();   // warp_sum reuse next row
    }
}

// ---------------------------------------------------------------------------
// Kernel 4: gather per-edge output, 4 edges per thread.  PDL secondary.
// ---------------------------------------------------------------------------
__global__ __launch_bounds__(512) void k_gather(const int4* __restrict__ src4,
                                                float4* __restrict__ out4, int E4) {
    int e = blockIdx.x * 512 + threadIdx.x;
    cudaGridDependencySynchronize();   // g_s ready
    if (e < E4) {
        int4 c = src4[e];
        float4 o;
        o.x = g_s[c.x];
        o.y = g_s[c.y];
        o.z = g_s[c.z];
        o.w = g_s[c.w];
        out4[e] = o;
    }
}

// ---------------------------------------------------------------------------
// launch helper: PDL launch (programmatic stream serialization)
// ---------------------------------------------------------------------------
template <typename... Args>
static inline void launch_pdl(void (*kern)(Args...), dim3 grid, dim3 block,
                              Args... args) {
    cudaLaunchAttribute attr[1];
    attr[0].id = cudaLaunchAttributeProgrammaticStreamSerialization;
    attr[0].val.programmaticStreamSerializationAllowed = 1;
    cudaLaunchConfig_t cfg{};
    cfg.gridDim = grid;
    cfg.blockDim = block;
    cfg.dynamicSmemBytes = 0;
    cfg.stream = 0;
    cfg.attrs = attr;
    cfg.numAttrs = 1;
    cudaLaunchKernelEx(&cfg, kern, args...);
}

// ---------------------------------------------------------------------------
// launch
// Inputs (metadata order): col, values, adj, src_nodes,
//                          w1e, b1e, w2e, b2e, w1n, b1n, w2n, b2n
// ---------------------------------------------------------------------------
extern "C" void kernel_launch(void* const* d_in, const int* in_sizes, int n_in,
                              void* d_out, int out_size) {
    const int*   col       = (const int*)d_in[0];
    const float* values    = (const float*)d_in[1];
    const float* adj       = (const float*)d_in[2];
    const int*   src_nodes = (const int*)d_in[3];
    const float* w1e = (const float*)d_in[4];
    const float* b1e = (const float*)d_in[5];
    const float* w2e = (const float*)d_in[6];
    const float* b2e = (const float*)d_in[7];
    const float* w1n = (const float*)d_in[8];
    const float* b1n = (const float*)d_in[9];
    const float* w2n = (const float*)d_in[10];
    const float* b2n = (const float*)d_in[11];
    float* out = (float*)d_out;

    const int nnz = in_sizes[0];   // 262144
    const int E   = in_sizes[3];   // 32768, divisible by 4
    const int E4  = E / 4;

    // primary: plain launch
    k_edge_scatter<<<(nnz + 255) / 256, 256>>>(
        col, values, w1e, b1e, w2e, b2e, nnz);

    // dependents: PDL
    launch_pdl(k_node_mlp, dim3((N_NODES + 511) / 512), dim3(512),
               w1n, b1n, w2n, b2n);
    launch_pdl(k_row_score, dim3(GRID_RS), dim3(256), adj);
    launch_pdl(k_gather, dim3((E4 + 511) / 512), dim3(512),
               (const int4*)src_nodes, (float4*)out, E4);
}

// round 10
// speedup vs baseline: 1.2705x; 1.0124x over previous
#include <cuda_runtime.h>

#define N_NODES 8192
#define NV4 (N_NODES / 4)       // 2048 float4 per row
#define PSI 64
#define GRID_RS 1184            // 148 SMs x 8 blocks, grid-stride over rows

// __device__ scratch (no allocations allowed).
// g_agg zero-init at load; node_mlp reads-then-zeros it each replay.
__device__ float g_agg[N_NODES];
__device__ float g_t[N_NODES];
__device__ float g_s[N_NODES];

// ---------------------------------------------------------------------------
// Kernel 1: edge MLP + scatter-add by col.
// Algebraic fast path: with zero hidden bias (verified on device),
//   f(v) = v*Cp + b2  (v >= 0),   f(v) = v*Cn + b2  (v < 0)
// where Cp/Cn sum w1j*w2j over positive/negative w1j.  Generic 64-term
// fallback keeps the kernel exact for arbitrary inputs.
// ---------------------------------------------------------------------------
__global__ __launch_bounds__(256) void k_edge_scatter(
        const int* __restrict__ col,
        const float* __restrict__ values,
        const float* __restrict__ w1,
        const float* __restrict__ b1,
        const float* __restrict__ w2,
        const float* __restrict__ b2,
        int nnz) {
    __shared__ float sw1[PSI], sb1[PSI], sw2[PSI];
    __shared__ float sCp, sCn, sb2;
    __shared__ int sfast;
    if (threadIdx.x < PSI) {
        sw1[threadIdx.x] = w1[threadIdx.x];
        sb1[threadIdx.x] = b1[threadIdx.x];
        sw2[threadIdx.x] = w2[threadIdx.x];
    }
    if (threadIdx.x == 0) sb2 = b2[0];
    __syncthreads();
    if (threadIdx.x == 0) {
        float cp = 0.0f, cn = 0.0f;
        int ok = 1;
#pragma unroll
        for (int j = 0; j < PSI; j++) {
            float w = sw1[j];
            float p = w * sw2[j];
            if (w > 0.0f) cp += p;
            else if (w < 0.0f) cn += p;
            if (sb1[j] != 0.0f) ok = 0;
        }
        sCp = cp; sCn = cn; sfast = ok;
    }
    __syncthreads();

    int i = blockIdx.x * 256 + threadIdx.x;
    if (i >= nnz) return;
    float v = values[i];
    float feat;
    if (sfast) {
        feat = fmaf(v, (v >= 0.0f) ? sCp : sCn, sb2);
    } else {
        float p0 = 0.0f, p1 = 0.0f, p2 = 0.0f, p3 = 0.0f;
#pragma unroll
        for (int j = 0; j < PSI; j += 4) {
            p0 = fmaf(fmaxf(fmaf(v, sw1[j+0], sb1[j+0]), 0.0f), sw2[j+0], p0);
            p1 = fmaf(fmaxf(fmaf(v, sw1[j+1], sb1[j+1]), 0.0f), sw2[j+1], p1);
            p2 = fmaf(fmaxf(fmaf(v, sw1[j+2], sb1[j+2]), 0.0f), sw2[j+2], p2);
            p3 = fmaf(fmaxf(fmaf(v, sw1[j+3], sb1[j+3]), 0.0f), sw2[j+3], p3);
        }
        feat = sb2 + (p0 + p1) + (p2 + p3);
    }
    atomicAdd(&g_agg[col[i]], feat);
}

// ---------------------------------------------------------------------------
// Kernel 2: node MLP, store struct^2, re-zero g_agg for the next replay.
// PDL secondary.  (8192 items — compute here is negligible, keep generic.)
// ---------------------------------------------------------------------------
__global__ __launch_bounds__(512) void k_node_mlp(
        const float* __restrict__ w1,
        const float* __restrict__ b1,
        const float* __restrict__ w2,
        const float* __restrict__ b2) {
    __shared__ float sw1[PSI], sb1[PSI], sw2[PSI], sb2;
    if (threadIdx.x < PSI) {
        sw1[threadIdx.x] = w1[threadIdx.x];
        sb1[threadIdx.x] = b1[threadIdx.x];
        sw2[threadIdx.x] = w2[threadIdx.x];
    }
    if (threadIdx.x == 0) sb2 = b2[0];
    __syncthreads();

    cudaGridDependencySynchronize();   // all g_agg atomics visible

    int i = blockIdx.x * 512 + threadIdx.x;
    if (i >= N_NODES) return;
    float x = g_agg[i];
    g_agg[i] = 0.0f;              // reset for next graph replay
    float p0 = 0.0f, p1 = 0.0f, p2 = 0.0f, p3 = 0.0f;
#pragma unroll
    for (int j = 0; j < PSI; j += 4) {
        p0 = fmaf(fmaxf(fmaf(x, sw1[j+0], sb1[j+0]), 0.0f), sw2[j+0], p0);
        p1 = fmaf(fmaxf(fmaf(x, sw1[j+1], sb1[j+1]), 0.0f), sw2[j+1], p1);
        p2 = fmaf(fmaxf(fmaf(x, sw1[j+2], sb1[j+2]), 0.0f), sw2[j+2], p2);
        p3 = fmaf(fmaxf(fmaf(x, sw1[j+3], sb1[j+3]), 0.0f), sw2[j+3], p3);
    }
    float acc = sb2 + (p0 + p1) + (p2 + p3);
    g_t[i] = acc * acc;
}

// ---------------------------------------------------------------------------
// Kernel 3: row score.  s[r] = sum_n adj[r,n]^2 * t[n]
// Grid-stride over rows, grid = 1184 (8 blocks/SM), low-register 1-row body
// (occ ~95%).  At the ~6.35 TB/s streaming ceiling.  PDL secondary.
// ---------------------------------------------------------------------------
__global__ __launch_bounds__(256, 8) void k_row_score(const float* __restrict__ adj) {
    __shared__ float warp_sum[8];
    const float4* __restrict__ tv = reinterpret_cast<const float4*>(g_t);

    cudaGridDependencySynchronize();   // g_t ready

    for (int row = blockIdx.x; row < N_NODES; row += GRID_RS) {
        const float4* __restrict__ a =
            reinterpret_cast<const float4*>(adj + (size_t)row * N_NODES);
        float acc = 0.0f;
#pragma unroll 4
        for (int i = threadIdx.x; i < NV4; i += 256) {
            float4 av = __ldcs(&a[i]);
            float4 tw = __ldg(&tv[i]);
            acc = fmaf(av.x * av.x, tw.x, acc);
            acc = fmaf(av.y * av.y, tw.y, acc);
            acc = fmaf(av.z * av.z, tw.z, acc);
            acc = fmaf(av.w * av.w, tw.w, acc);
        }
#pragma unroll
        for (int off = 16; off > 0; off >>= 1)
            acc += __shfl_down_sync(0xffffffffu, acc, off);
        if ((threadIdx.x & 31) == 0) warp_sum[threadIdx.x >> 5] = acc;
        __syncthreads();
        if (threadIdx.x < 8) {
            float v = warp_sum[threadIdx.x];
#pragma unroll
            for (int off = 4; off > 0; off >>= 1)
                v += __shfl_down_sync(0xffu, v, off);
            if (threadIdx.x == 0) g_s[row] = v;
        }
        __syncthreads();   // warp_sum reuse next row
    }
}

// ---------------------------------------------------------------------------
// Kernel 4: gather per-edge output, 1 edge/thread over 128 blocks (spread
// across SMs; g_s is L2-hot).  PDL secondary.
// ---------------------------------------------------------------------------
__global__ __launch_bounds__(256) void k_gather(const int* __restrict__ src_nodes,
                                                float* __restrict__ out, int E) {
    int e = blockIdx.x * 256 + threadIdx.x;
    cudaGridDependencySynchronize();   // g_s ready
    if (e < E) out[e] = g_s[src_nodes[e]];
}

// ---------------------------------------------------------------------------
// launch helper: PDL launch (programmatic stream serialization)
// ---------------------------------------------------------------------------
template <typename... Args>
static inline void launch_pdl(void (*kern)(Args...), dim3 grid, dim3 block,
                              Args... args) {
    cudaLaunchAttribute attr[1];
    attr[0].id = cudaLaunchAttributeProgrammaticStreamSerialization;
    attr[0].val.programmaticStreamSerializationAllowed = 1;
    cudaLaunchConfig_t cfg{};
    cfg.gridDim = grid;
    cfg.blockDim = block;
    cfg.dynamicSmemBytes = 0;
    cfg.stream = 0;
    cfg.attrs = attr;
    cfg.numAttrs = 1;
    cudaLaunchKernelEx(&cfg, kern, args...);
}

// ---------------------------------------------------------------------------
// launch
// Inputs (metadata order): col, values, adj, src_nodes,
//                          w1e, b1e, w2e, b2e, w1n, b1n, w2n, b2n
// ---------------------------------------------------------------------------
extern "C" void kernel_launch(void* const* d_in, const int* in_sizes, int n_in,
                              void* d_out, int out_size) {
    const int*   col       = (const int*)d_in[0];
    const float* values    = (const float*)d_in[1];
    const float* adj       = (const float*)d_in[2];
    const int*   src_nodes = (const int*)d_in[3];
    const float* w1e = (const float*)d_in[4];
    const float* b1e = (const float*)d_in[5];
    const float* w2e = (const float*)d_in[6];
    const float* b2e = (const float*)d_in[7];
    const float* w1n = (const float*)d_in[8];
    const float* b1n = (const float*)d_in[9];
    const float* w2n = (const float*)d_in[10];
    const float* b2n = (const float*)d_in[11];
    float* out = (float*)d_out;

    const int nnz = in_sizes[0];   // 262144
    const int E   = in_sizes[3];   // 32768

    // primary: plain launch
    k_edge_scatter<<<(nnz + 255) / 256, 256>>>(
        col, values, w1e, b1e, w2e, b2e, nnz);

    // dependents: PDL
    launch_pdl(k_node_mlp, dim3((N_NODES + 511) / 512), dim3(512),
               w1n, b1n, w2n, b2n);
    launch_pdl(k_row_score, dim3(GRID_RS), dim3(256), adj);
    launch_pdl(k_gather, dim3((E + 255) / 256), dim3(256),
               src_nodes, out, E);
}